// round 1
// baseline (speedup 1.0000x reference)
#include <cuda_runtime.h>
#include <cuda_bf16.h>

// ---------------------------------------------------------------------------
// AdaptiveRankingLoss: mean over valid pairs (|t_i - t_j| >= 0.05) of
//   0.5*(s_i+s_j) * relu(-sign(t_i-t_j)*(p_i-p_j) + 0.08*ms*clip(|t_i-t_j|,0.1,1))
// Summand is symmetric in (i,j), diagonal auto-excluded, so the full-matrix
// ratio equals the upper-triangle ratio.
// ---------------------------------------------------------------------------

__device__ float        g_total;
__device__ unsigned int g_count;

__global__ void arl_zero_kernel() {
    g_total = 0.0f;
    g_count = 0u;
}

#define ARL_TB    256   // threads per CTA (rows per CTA)
#define ARL_CHUNK 256   // columns per CTA tile

__global__ __launch_bounds__(ARL_TB)
void arl_main_kernel(const float* __restrict__ pred,
                     const float* __restrict__ tgt,
                     const float* __restrict__ snr,
                     const int*   __restrict__ msptr,
                     int n)
{
    __shared__ float4 tile[ARL_CHUNK];

    // Decode margin_scale robustly: small int bit pattern -> int, else float.
    int   iv = *msptr;
    float ms = (iv > -100000 && iv < 100000) ? (float)iv : __int_as_float(iv);
    const float mbase = 0.08f * ms;

    const int row = blockIdx.x * ARL_TB + threadIdx.x;
    const int c0  = blockIdx.y * ARL_CHUNK;
    const int kmax = min(ARL_CHUNK, n - c0);

    // Stage column tile: (target, prediction, 0.5*snr)
    for (int k = threadIdx.x; k < kmax; k += ARL_TB) {
        int j = c0 + k;
        tile[k] = make_float4(tgt[j], pred[j], 0.5f * snr[j], 0.0f);
    }
    __syncthreads();

    float        total = 0.0f;
    unsigned int cnt   = 0u;

    if (row < n) {
        const float ti  = tgt[row];
        const float pi  = pred[row];
        const float hsi = 0.5f * snr[row];

        #pragma unroll 8
        for (int k = 0; k < kmax; ++k) {
            float4 v  = tile[k];
            float td  = ti - v.x;
            float ad  = fabsf(td);
            float pd  = pi - v.y;
            float spd = (td > 0.0f) ? -pd : pd;        // -sign(td)*pd (td!=0 when valid)
            float mrg = mbase * fminf(fmaxf(ad, 0.1f), 1.0f);
            float vio = fmaxf(spd + mrg, 0.0f);
            if (ad >= 0.05f) {
                total = fmaf(hsi + v.z, vio, total);
                cnt++;
            }
        }
    }

    // Warp reduce, then one atomic per warp.
    #pragma unroll
    for (int o = 16; o; o >>= 1) {
        total += __shfl_xor_sync(0xFFFFFFFFu, total, o);
        cnt   += __shfl_xor_sync(0xFFFFFFFFu, cnt,   o);
    }
    if ((threadIdx.x & 31) == 0) {
        atomicAdd(&g_total, total);
        atomicAdd(&g_count, cnt);
    }
}

__global__ void arl_final_kernel(float* __restrict__ out) {
    out[0] = (g_count > 0u) ? (g_total / (float)g_count) : 0.0f;
}

extern "C" void kernel_launch(void* const* d_in, const int* in_sizes, int n_in,
                              void* d_out, int out_size)
{
    const float* pred = (const float*)d_in[0];
    const float* tgt  = (const float*)d_in[1];
    const float* snr  = (const float*)d_in[2];
    const int*   ms   = (const int*)  d_in[3];
    float*       out  = (float*)d_out;
    const int n = in_sizes[0];

    arl_zero_kernel<<<1, 1>>>();

    dim3 grid((n + ARL_TB - 1) / ARL_TB, (n + ARL_CHUNK - 1) / ARL_CHUNK);
    arl_main_kernel<<<grid, ARL_TB>>>(pred, tgt, snr, ms, n);

    arl_final_kernel<<<1, 1>>>(out);
}

// round 2
// speedup vs baseline: 1.3628x; 1.3628x over previous
#include <cuda_runtime.h>
#include <cuda_bf16.h>

// ---------------------------------------------------------------------------
// AdaptiveRankingLoss: mean over valid pairs (|t_i - t_j| >= 0.05) of
//   0.5*(s_i+s_j) * relu(-sign(t_i-t_j)*(p_i-p_j) + 0.08*ms*clip(|t_i-t_j|,0.1,1))
// Summand symmetric in (i,j), diagonal auto-excluded -> full-matrix ratio ==
// triangle ratio. We evaluate only the upper-triangular 256x256 block grid:
// diagonal blocks weight 1, strictly-upper blocks weight 2.
// Per-block partials -> fixed slots in __device__ arrays (no atomics, no
// zero kernel). Epilogue reduces the partials.
// ---------------------------------------------------------------------------

#define ARL_TILE   256           // square tile edge (rows = cols)
#define ARL_TB     128           // threads per CTA; each thread owns 2 rows
#define ARL_MAXNB  64            // supports n <= 16384
#define ARL_MAXBLK (ARL_MAXNB * (ARL_MAXNB + 1) / 2)

__device__ float        g_pt[ARL_MAXBLK];   // per-block weighted totals
__device__ unsigned int g_pc[ARL_MAXBLK];   // per-block weighted counts

__global__ __launch_bounds__(ARL_TB)
void arl_main_kernel(const float* __restrict__ pred,
                     const float* __restrict__ tgt,
                     const float* __restrict__ snr,
                     const int*   __restrict__ msptr,
                     int n, int nb)
{
    __shared__ float4 tile[ARL_TILE];
    __shared__ float  s_tot[ARL_TB / 32];
    __shared__ unsigned int s_cnt[ARL_TB / 32];

    // Linear block id -> (bi, bj) with bi <= bj (upper triangle of nb x nb).
    int b = blockIdx.x;
    int bi = 0;
    while (b >= nb - bi) { b -= nb - bi; ++bi; }
    const int bj = bi + b;

    // margin_scale: small-int bit pattern -> int, else float bits.
    int   iv = *msptr;
    float ms = (iv > -100000 && iv < 100000) ? (float)iv : __int_as_float(iv);
    const float mbase = 0.08f * ms;

    const int c0   = bj * ARL_TILE;
    const int kmax = min(ARL_TILE, n - c0);

    // Stage column tile: (target, prediction, 0.5*snr)
    for (int k = threadIdx.x; k < kmax; k += ARL_TB) {
        int j = c0 + k;
        tile[k] = make_float4(tgt[j], pred[j], 0.5f * snr[j], 0.0f);
    }
    __syncthreads();

    const int row0 = bi * ARL_TILE + threadIdx.x;
    const int row1 = row0 + ARL_TB;

    float        total = 0.0f;
    unsigned int cnt   = 0u;

    if (row1 < n) {
        const float t0 = tgt[row0],  p0 = pred[row0], h0 = 0.5f * snr[row0];
        const float t1 = tgt[row1],  p1 = pred[row1], h1 = 0.5f * snr[row1];

        #pragma unroll 4
        for (int k = 0; k < kmax; ++k) {
            float4 v = tile[k];
            // row 0
            {
                float td  = t0 - v.x;
                float ad  = fabsf(td);
                float pd  = p0 - v.y;
                float spd = (td > 0.0f) ? -pd : pd;
                float cl  = fminf(fmaxf(ad, 0.1f), 1.0f);
                float vio = fmaxf(fmaf(mbase, cl, spd), 0.0f);
                if (ad >= 0.05f) { total = fmaf(h0 + v.z, vio, total); cnt++; }
            }
            // row 1
            {
                float td  = t1 - v.x;
                float ad  = fabsf(td);
                float pd  = p1 - v.y;
                float spd = (td > 0.0f) ? -pd : pd;
                float cl  = fminf(fmaxf(ad, 0.1f), 1.0f);
                float vio = fmaxf(fmaf(mbase, cl, spd), 0.0f);
                if (ad >= 0.05f) { total = fmaf(h1 + v.z, vio, total); cnt++; }
            }
        }
    } else if (row0 < n) {
        const float t0 = tgt[row0], p0 = pred[row0], h0 = 0.5f * snr[row0];
        #pragma unroll 4
        for (int k = 0; k < kmax; ++k) {
            float4 v = tile[k];
            float td  = t0 - v.x;
            float ad  = fabsf(td);
            float pd  = p0 - v.y;
            float spd = (td > 0.0f) ? -pd : pd;
            float cl  = fminf(fmaxf(ad, 0.1f), 1.0f);
            float vio = fmaxf(fmaf(mbase, cl, spd), 0.0f);
            if (ad >= 0.05f) { total = fmaf(h0 + v.z, vio, total); cnt++; }
        }
    }

    // Warp reduce
    #pragma unroll
    for (int o = 16; o; o >>= 1) {
        total += __shfl_xor_sync(0xFFFFFFFFu, total, o);
        cnt   += __shfl_xor_sync(0xFFFFFFFFu, cnt,   o);
    }
    const int wid = threadIdx.x >> 5;
    if ((threadIdx.x & 31) == 0) { s_tot[wid] = total; s_cnt[wid] = cnt; }
    __syncthreads();

    if (threadIdx.x == 0) {
        float        bt = 0.0f;
        unsigned int bc = 0u;
        #pragma unroll
        for (int w = 0; w < ARL_TB / 32; ++w) { bt += s_tot[w]; bc += s_cnt[w]; }
        const float wgt = (bi == bj) ? 1.0f : 2.0f;
        g_pt[blockIdx.x] = bt * wgt;
        g_pc[blockIdx.x] = (bi == bj) ? bc : 2u * bc;
    }
}

__global__ __launch_bounds__(256)
void arl_final_kernel(float* __restrict__ out, int nblk)
{
    __shared__ float        s_tot[8];
    __shared__ unsigned int s_cnt[8];

    float        total = 0.0f;
    unsigned int cnt   = 0u;
    for (int i = threadIdx.x; i < nblk; i += 256) {
        total += g_pt[i];
        cnt   += g_pc[i];
    }
    #pragma unroll
    for (int o = 16; o; o >>= 1) {
        total += __shfl_xor_sync(0xFFFFFFFFu, total, o);
        cnt   += __shfl_xor_sync(0xFFFFFFFFu, cnt,   o);
    }
    const int wid = threadIdx.x >> 5;
    if ((threadIdx.x & 31) == 0) { s_tot[wid] = total; s_cnt[wid] = cnt; }
    __syncthreads();
    if (threadIdx.x == 0) {
        float        t = 0.0f;
        unsigned int c = 0u;
        #pragma unroll
        for (int w = 0; w < 8; ++w) { t += s_tot[w]; c += s_cnt[w]; }
        out[0] = (c > 0u) ? (t / (float)c) : 0.0f;
    }
}

extern "C" void kernel_launch(void* const* d_in, const int* in_sizes, int n_in,
                              void* d_out, int out_size)
{
    const float* pred = (const float*)d_in[0];
    const float* tgt  = (const float*)d_in[1];
    const float* snr  = (const float*)d_in[2];
    const int*   ms   = (const int*)  d_in[3];
    float*       out  = (float*)d_out;
    const int n  = in_sizes[0];
    const int nb = (n + ARL_TILE - 1) / ARL_TILE;
    const int nblk = nb * (nb + 1) / 2;

    arl_main_kernel<<<nblk, ARL_TB>>>(pred, tgt, snr, ms, n, nb);
    arl_final_kernel<<<1, 256>>>(out, nblk);
}